// round 9
// baseline (speedup 1.0000x reference)
#include <cuda_runtime.h>
#include <cstddef>

#define QLEN 1024
#define MLEN 1024
#define KLEN 2048
#define BSZ  4
#define DM   1024
#define NH   16
#define DH   64

// ---------------- scratch (device globals; allocation is forbidden) ----------------
__device__ float g_Q [(size_t)BSZ * NH * QLEN * DH];   // [b][n][i][d]
__device__ float g_K [(size_t)BSZ * NH * KLEN * DH];   // [b][n][j][d]
__device__ float g_V [(size_t)BSZ * NH * KLEN * DH];   // [b][n][j][d]
__device__ float g_RK[(size_t)NH * KLEN * DH];         // [n][jr][d]
__device__ float g_AV[(size_t)QLEN * BSZ * DM];        // attn_vec, row = i*BSZ+b
__device__ float g_Y [(size_t)QLEN * BSZ * DM];        // w + attn_out (pre-LN)

#define MODE_Q 0
#define MODE_K 1
#define MODE_V 2
#define MODE_R 3
#define MODE_O 4

// ---------------- SGEMM: C[M,1024] = A[M,1024] @ W[1024,1024] + bias ----------------
#define BM 128
#define BN 128
#define BK 16
#define APAD 4

template <int MODE>
__global__ __launch_bounds__(256, 2)
void sgemm_kernel(const float* __restrict__ A0, const float* __restrict__ A1,
                  const float* __restrict__ W, const float* __restrict__ bias,
                  const float* __restrict__ addend)
{
    __shared__ float As[BK][BM + APAD];   // transposed A tile
    __shared__ float Bs[BK][BN];
    const int t  = threadIdx.x;
    const int m0 = blockIdx.y * BM;
    const int n0 = blockIdx.x * BN;
    const int tx = t & 15;
    const int ty = t >> 4;

    // A-tile loader: each thread loads 8 contiguous k's of one row
    const int am   = t >> 1;              // local row 0..127
    const int arow = m0 + am;
    const int acol = (t & 1) * 8;
    const float* Aptr;
    if (MODE == MODE_K || MODE == MODE_V) {
        // virtual concat cat = [mems; w], flat row = pos*BSZ + b
        Aptr = (arow < MLEN * BSZ) ? (A0 + (size_t)arow * DM)
                                   : (A1 + (size_t)(arow - MLEN * BSZ) * DM);
    } else if (MODE == MODE_O) {
        Aptr = g_AV + (size_t)arow * DM;
    } else {
        Aptr = A0 + (size_t)arow * DM;
    }
    const int brow = t >> 4;              // 0..15
    const int bcol = (t & 15) * 8;

    float acc[8][8];
#pragma unroll
    for (int i = 0; i < 8; i++)
#pragma unroll
        for (int j = 0; j < 8; j++) acc[i][j] = 0.f;

    for (int k0 = 0; k0 < DM; k0 += BK) {
        float4 a0 = *(const float4*)(Aptr + k0 + acol);
        float4 a1 = *(const float4*)(Aptr + k0 + acol + 4);
        float4 b0 = *(const float4*)(W + (size_t)(k0 + brow) * DM + n0 + bcol);
        float4 b1 = *(const float4*)(W + (size_t)(k0 + brow) * DM + n0 + bcol + 4);
        __syncthreads();   // previous iteration's compute done
        As[acol + 0][am] = a0.x; As[acol + 1][am] = a0.y;
        As[acol + 2][am] = a0.z; As[acol + 3][am] = a0.w;
        As[acol + 4][am] = a1.x; As[acol + 5][am] = a1.y;
        As[acol + 6][am] = a1.z; As[acol + 7][am] = a1.w;
        *(float4*)&Bs[brow][bcol]     = b0;
        *(float4*)&Bs[brow][bcol + 4] = b1;
        __syncthreads();
#pragma unroll
        for (int k = 0; k < BK; k++) {
            float a[8], b[8];
            *(float4*)(a)     = *(const float4*)&As[k][ty * 8];
            *(float4*)(a + 4) = *(const float4*)&As[k][ty * 8 + 4];
            *(float4*)(b)     = *(const float4*)&Bs[k][tx * 8];
            *(float4*)(b + 4) = *(const float4*)&Bs[k][tx * 8 + 4];
#pragma unroll
            for (int i = 0; i < 8; i++)
#pragma unroll
                for (int j = 0; j < 8; j++)
                    acc[i][j] = fmaf(a[i], b[j], acc[i][j]);
        }
    }

    // epilogue: bias + per-mode scatter into head-major layouts
#pragma unroll
    for (int i = 0; i < 8; i++) {
        const int row = m0 + ty * 8 + i;
#pragma unroll
        for (int j = 0; j < 8; j++) {
            const int col = n0 + tx * 8 + j;
            float v = acc[i][j] + bias[col];
            if (MODE == MODE_O) {
                g_Y[(size_t)row * DM + col] = v + addend[(size_t)row * DM + col];
            } else if (MODE == MODE_R) {
                const int nn = col >> 6, d = col & 63;
                g_RK[((size_t)nn * KLEN + row) * DH + d] = v;
            } else if (MODE == MODE_Q) {
                const int ip = row >> 2, bb = row & 3;
                const int nn = col >> 6, d = col & 63;
                g_Q[(((size_t)bb * NH + nn) * QLEN + ip) * DH + d] = v;
            } else {  // K or V
                const int jp = row >> 2, bb = row & 3;
                const int nn = col >> 6, d = col & 63;
                float* dst = (MODE == MODE_K) ? g_K : g_V;
                dst[(((size_t)bb * NH + nn) * KLEN + jp) * DH + d] = v;
            }
        }
    }
}

// ---------------- flash attention with Transformer-XL rel-shift ----------------
// score[i,j] = 0.125*((q_i+bw_n)·k_j + (q_i+br_n)·rk[j+QLEN-1-i]), masked if j > i+MLEN
#define QT_STRIDE 65
#define KS_STRIDE 68
#define RS_STRIDE 129
#define VS_STRIDE 68
#define OFF_QT 0
#define OFF_BW (OFF_QT + 64 * QT_STRIDE)           // 4160
#define OFF_BR (OFF_BW + 64)                       // 4224
#define OFF_KS (OFF_BR + 64)                       // 4288
#define OFF_RS (OFF_KS + 64 * KS_STRIDE)           // 8640
#define OFF_VS (OFF_RS + 64 * RS_STRIDE)           // 16896
#define ATTN_SMEM_FLOATS (OFF_VS + 64 * VS_STRIDE) // 21248
#define ATTN_SMEM_BYTES  (ATTN_SMEM_FLOATS * 4)    // 84992

__global__ __launch_bounds__(256, 1)
void attn_kernel(const float* __restrict__ rwb, const float* __restrict__ rrb)
{
    extern __shared__ float sm[];
    float* qT  = sm + OFF_QT;   // [d][row]
    float* bw  = sm + OFF_BW;   // [d]
    float* brr = sm + OFF_BR;   // [d]
    float* KsT = sm + OFF_KS;   // [d][col]
    float* RsT = sm + OFF_RS;   // [d][ridx 0..127]
    float* Vs  = sm + OFF_VS;   // [col][d]

    const int t  = threadIdx.x;
    const int i0 = blockIdx.x * 64;
    const int h  = blockIdx.y;
    const int b  = h >> 4;
    const int n  = h & 15;

    const float* Qh = g_Q  + ((size_t)b * NH + n) * QLEN * DH;
    const float* Kh = g_K  + ((size_t)b * NH + n) * KLEN * DH;
    const float* Vh = g_V  + ((size_t)b * NH + n) * KLEN * DH;
    const float* Rh = g_RK + (size_t)n * KLEN * DH;

    if (t < 64) {
        bw[t]  = rwb[n * DH + t];
        brr[t] = rrb[n * DH + t];
    }
    for (int q = t; q < 64 * 16; q += 256) {       // quad items: 64 rows x 16 d-groups
        const int r = q >> 4, d = (q & 15) * 4;
        float4 q4 = *(const float4*)(Qh + (size_t)(i0 + r) * DH + d);
        qT[(d + 0) * QT_STRIDE + r] = q4.x;
        qT[(d + 1) * QT_STRIDE + r] = q4.y;
        qT[(d + 2) * QT_STRIDE + r] = q4.z;
        qT[(d + 3) * QT_STRIDE + r] = q4.w;
    }

    const int row   = t >> 2;   // 0..63
    const int cg    = t & 3;    // 16-column group
    const int ibase = i0 + row;
    float m = -1e30f, l = 0.f;
    float acc[64];
#pragma unroll
    for (int d = 0; d < 64; d++) acc[d] = 0.f;

    const int ntile = blockIdx.x + 17;   // keys needed: j <= i + MLEN
    for (int jt = 0; jt < ntile; jt++) {
        const int j0 = jt * 64;
        __syncthreads();   // previous tile consumed (also orders q/bias stores, jt=0)

        for (int q = t; q < 64 * 16; q += 256) {   // 64 cols x 16 d-groups
            const int c = q >> 4, d = (q & 15) * 4;
            float4 k4 = *(const float4*)(Kh + (size_t)(j0 + c) * DH + d);
            KsT[(d + 0) * KS_STRIDE + c] = k4.x;
            KsT[(d + 1) * KS_STRIDE + c] = k4.y;
            KsT[(d + 2) * KS_STRIDE + c] = k4.z;
            KsT[(d + 3) * KS_STRIDE + c] = k4.w;
            *(float4*)(Vs + (size_t)c * VS_STRIDE + d) =
                *(const float4*)(Vh + (size_t)(j0 + c) * DH + d);
        }
        // shifted RK window: rk index = j + 1023 - i = rbase + (localcol - localrow + 63)
        const int rbase = j0 - i0 + (QLEN - 64);    // >= 0 always
        for (int q = t; q < 128 * 16; q += 256) {   // 128 ridx x 16 d-groups
            const int ri = q & 127, d = (q >> 7) * 4;
            const int jr = rbase + ri;
            float4 r4 = make_float4(0.f, 0.f, 0.f, 0.f);
            if (jr < KLEN) r4 = *(const float4*)(Rh + (size_t)jr * DH + d);
            RsT[(d + 0) * RS_STRIDE + ri] = r4.x;
            RsT[(d + 1) * RS_STRIDE + ri] = r4.y;
            RsT[(d + 2) * RS_STRIDE + ri] = r4.z;
            RsT[(d + 3) * RS_STRIDE + ri] = r4.w;
        }
        __syncthreads();

        float s[16];
#pragma unroll
        for (int jj = 0; jj < 16; jj++) s[jj] = 0.f;
#pragma unroll 4
        for (int d = 0; d < DH; d++) {
            const float qd = qT[d * QT_STRIDE + row];
            const float qv = qd + bw[d];
            const float rv = qd + brr[d];
            const float4* kp = (const float4*)(KsT + d * KS_STRIDE + cg * 16);
            float4 k0 = kp[0], k1 = kp[1], k2 = kp[2], k3 = kp[3];
            s[0]  = fmaf(qv, k0.x, s[0]);  s[1]  = fmaf(qv, k0.y, s[1]);
            s[2]  = fmaf(qv, k0.z, s[2]);  s[3]  = fmaf(qv, k0.w, s[3]);
            s[4]  = fmaf(qv, k1.x, s[4]);  s[5]  = fmaf(qv, k1.y, s[5]);
            s[6]  = fmaf(qv, k1.z, s[6]);  s[7]  = fmaf(qv, k1.w, s[7]);
            s[8]  = fmaf(qv, k2.x, s[8]);  s[9]  = fmaf(qv, k2.y, s[9]);
            s[10] = fmaf(qv, k2.z, s[10]); s[11] = fmaf(qv, k2.w, s[11]);
            s[12] = fmaf(qv, k3.x, s[12]); s[13] = fmaf(qv, k3.y, s[13]);
            s[14] = fmaf(qv, k3.z, s[14]); s[15] = fmaf(qv, k3.w, s[15]);
            const float* rp = RsT + d * RS_STRIDE + (cg * 16 + 63 - row);
#pragma unroll
            for (int jj = 0; jj < 16; jj++) s[jj] = fmaf(rv, rp[jj], s[jj]);
        }

        // mask + scale (1/sqrt(64) = 0.125)
#pragma unroll
        for (int jj = 0; jj < 16; jj++) {
            const int j = j0 + cg * 16 + jj;
            s[jj] = (j <= ibase + MLEN) ? s[jj] * 0.125f : -1e30f;
        }
        // online softmax; row state shared across the 4 cg lanes (consecutive lanes)
        float tmax = s[0];
#pragma unroll
        for (int jj = 1; jj < 16; jj++) tmax = fmaxf(tmax, s[jj]);
        tmax = fmaxf(tmax, __shfl_xor_sync(0xffffffffu, tmax, 1));
        tmax = fmaxf(tmax, __shfl_xor_sync(0xffffffffu, tmax, 2));
        const float nm   = fmaxf(m, tmax);
        const float corr = __expf(m - nm);
        m = nm;
        float ps = 0.f;
#pragma unroll
        for (int jj = 0; jj < 16; jj++) { s[jj] = __expf(s[jj] - nm); ps += s[jj]; }
        l = l * corr + ps;
#pragma unroll
        for (int d = 0; d < 64; d++) acc[d] *= corr;
#pragma unroll
        for (int jj = 0; jj < 16; jj++) {
            const float pj = s[jj];
            const float4* vp = (const float4*)(Vs + (size_t)(cg * 16 + jj) * VS_STRIDE);
#pragma unroll
            for (int u = 0; u < 16; u++) {
                float4 vv = vp[u];
                acc[4 * u + 0] = fmaf(pj, vv.x, acc[4 * u + 0]);
                acc[4 * u + 1] = fmaf(pj, vv.y, acc[4 * u + 1]);
                acc[4 * u + 2] = fmaf(pj, vv.z, acc[4 * u + 2]);
                acc[4 * u + 3] = fmaf(pj, vv.w, acc[4 * u + 3]);
            }
        }
    }

    // reduce partials across the 4 cg lanes of each row
    l += __shfl_xor_sync(0xffffffffu, l, 1);
    l += __shfl_xor_sync(0xffffffffu, l, 2);
    const float inv = 1.f / l;
#pragma unroll
    for (int d = 0; d < 64; d++) {
        float v = acc[d];
        v += __shfl_xor_sync(0xffffffffu, v, 1);
        v += __shfl_xor_sync(0xffffffffu, v, 2);
        acc[d] = v;
    }
    // each cg lane writes its 16-dim slice; row-major [i*BSZ+b][n*64+d]
    float* outp = g_AV + ((size_t)(i0 + row) * BSZ + b) * DM + n * DH + cg * 16;
#pragma unroll
    for (int u = 0; u < 16; u++) outp[u] = acc[cg * 16 + u] * inv;
}

// ---------------- LayerNorm over last dim (1024) ----------------
__global__ __launch_bounds__(256)
void ln_kernel(const float* __restrict__ gam, const float* __restrict__ bet,
               float* __restrict__ out)
{
    __shared__ float rs[8], rq[8];
    const int row = blockIdx.x;
    const int t = threadIdx.x;
    const float4 v = ((const float4*)(g_Y + (size_t)row * DM))[t];
    float s = v.x + v.y + v.z + v.w;
    float q = v.x * v.x + v.y * v.y + v.z * v.z + v.w * v.w;
#pragma unroll
    for (int o = 16; o; o >>= 1) {
        s += __shfl_down_sync(0xffffffffu, s, o);
        q += __shfl_down_sync(0xffffffffu, q, o);
    }
    if ((t & 31) == 0) { rs[t >> 5] = s; rq[t >> 5] = q; }
    __syncthreads();
    if (t == 0) {
        float ss = 0.f, qq = 0.f;
#pragma unroll
        for (int i = 0; i < 8; i++) { ss += rs[i]; qq += rq[i]; }
        rs[0] = ss; rq[0] = qq;
    }
    __syncthreads();
    const float mu   = rs[0] * (1.f / 1024.f);
    const float var  = rq[0] * (1.f / 1024.f) - mu * mu;
    const float rstd = rsqrtf(var + 1e-5f);
    const float4 g4 = ((const float4*)gam)[t];
    const float4 b4 = ((const float4*)bet)[t];
    float4 o4;
    o4.x = (v.x - mu) * rstd * g4.x + b4.x;
    o4.y = (v.y - mu) * rstd * g4.y + b4.y;
    o4.z = (v.z - mu) * rstd * g4.z + b4.z;
    o4.w = (v.w - mu) * rstd * g4.w + b4.w;
    ((float4*)(out + (size_t)row * DM))[t] = o4;
}

// ---------------- launch ----------------
extern "C" void kernel_launch(void* const* d_in, const int* in_sizes, int n_in,
                              void* d_out, int out_size)
{
    const float* w    = (const float*)d_in[0];
    const float* r    = (const float*)d_in[1];
    const float* rwb  = (const float*)d_in[2];
    const float* rrb  = (const float*)d_in[3];
    const float* mems = (const float*)d_in[4];
    const float* Wq   = (const float*)d_in[5];
    const float* bq   = (const float*)d_in[6];
    const float* Wk   = (const float*)d_in[7];
    const float* bk   = (const float*)d_in[8];
    const float* Wv   = (const float*)d_in[9];
    const float* bv   = (const float*)d_in[10];
    const float* Wr   = (const float*)d_in[11];
    const float* br   = (const float*)d_in[12];
    const float* Wo   = (const float*)d_in[13];
    const float* bo   = (const float*)d_in[14];
    const float* lng  = (const float*)d_in[15];
    const float* lnb  = (const float*)d_in[16];
    float* out = (float*)d_out;

    cudaFuncSetAttribute(attn_kernel,
                         cudaFuncAttributeMaxDynamicSharedMemorySize, ATTN_SMEM_BYTES);

    const dim3 blk(256);
    // projections (independent; sequential on one stream)
    sgemm_kernel<MODE_Q><<<dim3(8, 32), blk>>>(w, nullptr, Wq, bq, nullptr);
    sgemm_kernel<MODE_K><<<dim3(8, 64), blk>>>(mems, w, Wk, bk, nullptr);
    sgemm_kernel<MODE_V><<<dim3(8, 64), blk>>>(mems, w, Wv, bv, nullptr);
    sgemm_kernel<MODE_R><<<dim3(8, 16), blk>>>(r, nullptr, Wr, br, nullptr);
    // attention: 16 q-tiles x 64 (b,n) heads
    attn_kernel<<<dim3(16, 64), blk, ATTN_SMEM_BYTES>>>(rwb, rrb);
    // output projection + residual, then LayerNorm
    sgemm_kernel<MODE_O><<<dim3(8, 32), blk>>>(nullptr, nullptr, Wo, bo, w);
    ln_kernel<<<QLEN * BSZ, 256>>>(lng, lnb, out);
}

// round 10
// speedup vs baseline: 2.6819x; 2.6819x over previous
#include <cuda_runtime.h>
#include <cstddef>

#define QLEN 1024
#define MLEN 1024
#define KLEN 2048
#define BSZ  4
#define DM   1024
#define NH   16
#define DH   64

// ---------------- scratch (device globals; allocation is forbidden) ----------------
__device__ float g_Q [(size_t)BSZ * NH * QLEN * DH];   // [b][n][i][d]
__device__ float g_K [(size_t)BSZ * NH * KLEN * DH];   // [b][n][j][d]
__device__ float g_V [(size_t)BSZ * NH * KLEN * DH];   // [b][n][j][d]
__device__ float g_RK[(size_t)NH * KLEN * DH];         // [n][jr][d]
__device__ float g_AV[(size_t)QLEN * BSZ * DM];        // attn_vec, row = i*BSZ+b
__device__ float g_Y [(size_t)QLEN * BSZ * DM];        // w + attn_out (pre-LN)

#define MODE_Q 0
#define MODE_K 1
#define MODE_V 2
#define MODE_R 3
#define MODE_O 4

// ---------------- SGEMM: C[M,1024] = A[M,1024] @ W[1024,1024] + bias ----------------
#define BM 128
#define BN 128
#define BK 16
#define APAD 4

template <int MODE>
__global__ __launch_bounds__(256, 2)
void sgemm_kernel(const float* __restrict__ A0, const float* __restrict__ A1,
                  const float* __restrict__ W, const float* __restrict__ bias,
                  const float* __restrict__ addend)
{
    __shared__ float As[BK][BM + APAD];   // transposed A tile
    __shared__ float Bs[BK][BN];
    const int t  = threadIdx.x;
    const int m0 = blockIdx.y * BM;
    const int n0 = blockIdx.x * BN;
    const int tx = t & 15;
    const int ty = t >> 4;

    const int am   = t >> 1;              // local row 0..127
    const int arow = m0 + am;
    const int acol = (t & 1) * 8;
    const float* Aptr;
    if (MODE == MODE_K || MODE == MODE_V) {
        Aptr = (arow < MLEN * BSZ) ? (A0 + (size_t)arow * DM)
                                   : (A1 + (size_t)(arow - MLEN * BSZ) * DM);
    } else if (MODE == MODE_O) {
        Aptr = g_AV + (size_t)arow * DM;
    } else {
        Aptr = A0 + (size_t)arow * DM;
    }
    const int brow = t >> 4;
    const int bcol = (t & 15) * 8;

    float acc[8][8];
#pragma unroll
    for (int i = 0; i < 8; i++)
#pragma unroll
        for (int j = 0; j < 8; j++) acc[i][j] = 0.f;

    for (int k0 = 0; k0 < DM; k0 += BK) {
        float4 a0 = *(const float4*)(Aptr + k0 + acol);
        float4 a1 = *(const float4*)(Aptr + k0 + acol + 4);
        float4 b0 = *(const float4*)(W + (size_t)(k0 + brow) * DM + n0 + bcol);
        float4 b1 = *(const float4*)(W + (size_t)(k0 + brow) * DM + n0 + bcol + 4);
        __syncthreads();
        As[acol + 0][am] = a0.x; As[acol + 1][am] = a0.y;
        As[acol + 2][am] = a0.z; As[acol + 3][am] = a0.w;
        As[acol + 4][am] = a1.x; As[acol + 5][am] = a1.y;
        As[acol + 6][am] = a1.z; As[acol + 7][am] = a1.w;
        *(float4*)&Bs[brow][bcol]     = b0;
        *(float4*)&Bs[brow][bcol + 4] = b1;
        __syncthreads();
#pragma unroll
        for (int k = 0; k < BK; k++) {
            float a[8], b[8];
            *(float4*)(a)     = *(const float4*)&As[k][ty * 8];
            *(float4*)(a + 4) = *(const float4*)&As[k][ty * 8 + 4];
            *(float4*)(b)     = *(const float4*)&Bs[k][tx * 8];
            *(float4*)(b + 4) = *(const float4*)&Bs[k][tx * 8 + 4];
#pragma unroll
            for (int i = 0; i < 8; i++)
#pragma unroll
                for (int j = 0; j < 8; j++)
                    acc[i][j] = fmaf(a[i], b[j], acc[i][j]);
        }
    }

#pragma unroll
    for (int i = 0; i < 8; i++) {
        const int row = m0 + ty * 8 + i;
#pragma unroll
        for (int j = 0; j < 8; j++) {
            const int col = n0 + tx * 8 + j;
            float v = acc[i][j] + bias[col];
            if (MODE == MODE_O) {
                g_Y[(size_t)row * DM + col] = v + addend[(size_t)row * DM + col];
            } else if (MODE == MODE_R) {
                const int nn = col >> 6, d = col & 63;
                g_RK[((size_t)nn * KLEN + row) * DH + d] = v;
            } else if (MODE == MODE_Q) {
                const int ip = row >> 2, bb = row & 3;
                const int nn = col >> 6, d = col & 63;
                g_Q[(((size_t)bb * NH + nn) * QLEN + ip) * DH + d] = v;
            } else {  // K or V
                const int jp = row >> 2, bb = row & 3;
                const int nn = col >> 6, d = col & 63;
                float* dst = (MODE == MODE_K) ? g_K : g_V;
                dst[(((size_t)bb * NH + nn) * KLEN + jp) * DH + d] = v;
            }
        }
    }
}

// ---------------- flash attention, register-tiled (4x4 per thread) ----------------
// score[i,j] = 0.125*((q_i+bw)·k_j + (q_i+br)·rk[j+QLEN-1-i]), masked if j > i+MLEN
// With qw = q+bw and db = br-bw:  score = 0.125*( qw·(k_j + r_{j-i}) + BDc[j-i] )
// where BDc[ri] = sum_d db[d]*R[d][ri] is a per-tile rank-1 precompute.
#define QT_S 68
#define KS_S 68
#define VS_S 68
#define PS_S 68
#define RS_S 129
#define OFF_QT 0
#define OFF_KS (OFF_QT + 64 * QT_S)     // 4352
#define OFF_VS (OFF_KS + 64 * KS_S)     // 8704
#define OFF_PS (OFF_VS + 64 * VS_S)     // 13056
#define OFF_RS (OFF_PS + 64 * PS_S)     // 17408
#define OFF_DB (OFF_RS + 64 * RS_S)     // 25664
#define OFF_BDC (OFF_DB + 64)           // 25728
#define ATTN_SMEM_FLOATS (OFF_BDC + 128)        // 25856
#define ATTN_SMEM_BYTES  (ATTN_SMEM_FLOATS * 4) // 103424

__global__ __launch_bounds__(256, 2)
void attn_kernel(const float* __restrict__ rwb, const float* __restrict__ rrb)
{
    extern __shared__ float sm[];
    float* qwT = sm + OFF_QT;   // [d][row], q + r_w_bias
    float* KsT = sm + OFF_KS;   // [d][col]
    float* Vs  = sm + OFF_VS;   // [col][d]
    float* Ps  = sm + OFF_PS;   // [row][col] softmax probs
    float* RsT = sm + OFF_RS;   // [d][ridx 0..127]
    float* db  = sm + OFF_DB;   // r_r_bias - r_w_bias
    float* BDc = sm + OFF_BDC;  // [ridx] rank-1 BD term

    const int t  = threadIdx.x;
    const int qt = 15 - (int)blockIdx.x;   // heavy q-tiles first
    const int i0 = qt * 64;
    const int h  = blockIdx.y;
    const int b  = h >> 4;
    const int n  = h & 15;
    const int tx = t & 15;      // col group (4 cols / 4 dims)
    const int ty = t >> 4;      // row group (4 rows)

    const float* Qh = g_Q  + ((size_t)b * NH + n) * QLEN * DH;
    const float* Kh = g_K  + ((size_t)b * NH + n) * KLEN * DH;
    const float* Vh = g_V  + ((size_t)b * NH + n) * KLEN * DH;
    const float* Rh = g_RK + (size_t)n * KLEN * DH;

    if (t < 64) db[t] = rrb[n * DH + t] - rwb[n * DH + t];
    for (int e = t; e < 64 * 16; e += 256) {
        const int r = e >> 4, d = (e & 15) * 4;
        float4 q4 = *(const float4*)(Qh + (size_t)(i0 + r) * DH + d);
        float4 w4 = *(const float4*)(rwb + n * DH + d);
        qwT[(d + 0) * QT_S + r] = q4.x + w4.x;
        qwT[(d + 1) * QT_S + r] = q4.y + w4.y;
        qwT[(d + 2) * QT_S + r] = q4.z + w4.z;
        qwT[(d + 3) * QT_S + r] = q4.w + w4.w;
    }

    float m[4], l[4], acc[4][4];
#pragma unroll
    for (int i = 0; i < 4; i++) {
        m[i] = -1e30f; l[i] = 0.f;
#pragma unroll
        for (int j = 0; j < 4; j++) acc[i][j] = 0.f;
    }

    const int dbase = tx * 4 - ty * 4 + 63;   // rk local idx = dbase + j - i, in [0,126]
    const int ntile = qt + 17;

    for (int jt = 0; jt < ntile; jt++) {
        const int j0 = jt * 64;
        __syncthreads();   // prior tile fully consumed

        for (int e = t; e < 64 * 16; e += 256) {
            const int c = e >> 4, d = (e & 15) * 4;
            float4 k4 = *(const float4*)(Kh + (size_t)(j0 + c) * DH + d);
            KsT[(d + 0) * KS_S + c] = k4.x;
            KsT[(d + 1) * KS_S + c] = k4.y;
            KsT[(d + 2) * KS_S + c] = k4.z;
            KsT[(d + 3) * KS_S + c] = k4.w;
            *(float4*)(Vs + (size_t)c * VS_S + d) =
                *(const float4*)(Vh + (size_t)(j0 + c) * DH + d);
        }
        const int rb = j0 - i0 + (QLEN - 64);   // >= 0
        for (int e = t; e < 128 * 16; e += 256) {
            const int ri = e & 127, d = (e >> 7) * 4;
            const int jr = rb + ri;
            float4 r4 = make_float4(0.f, 0.f, 0.f, 0.f);
            if (jr < KLEN) r4 = *(const float4*)(Rh + (size_t)jr * DH + d);
            RsT[(d + 0) * RS_S + ri] = r4.x;
            RsT[(d + 1) * RS_S + ri] = r4.y;
            RsT[(d + 2) * RS_S + ri] = r4.z;
            RsT[(d + 3) * RS_S + ri] = r4.w;
        }
        __syncthreads();

        if (t < 128) {   // rank-1 BD precompute
            float sum = 0.f;
#pragma unroll 8
            for (int d = 0; d < 64; d++) sum = fmaf(db[d], RsT[d * RS_S + t], sum);
            BDc[t] = sum;
        }
        __syncthreads();

        float s[4][4];
#pragma unroll
        for (int i = 0; i < 4; i++)
#pragma unroll
            for (int j = 0; j < 4; j++)
                s[i][j] = BDc[dbase + j - i];

#pragma unroll 4
        for (int d = 0; d < 64; d++) {
            float4 qv = *(const float4*)(qwT + d * QT_S + ty * 4);
            float4 kv = *(const float4*)(KsT + d * KS_S + tx * 4);
            const float* rp = RsT + d * RS_S + (dbase - 3);
            float rr[7];
#pragma unroll
            for (int o = 0; o < 7; o++) rr[o] = rp[o];
            float qq[4] = {qv.x, qv.y, qv.z, qv.w};
            float kk[4] = {kv.x, kv.y, kv.z, kv.w};
#pragma unroll
            for (int i = 0; i < 4; i++)
#pragma unroll
                for (int j = 0; j < 4; j++)
                    s[i][j] = fmaf(qq[i], kk[j] + rr[3 + j - i], s[i][j]);
        }

        // scale + mask (only the last tile has masked entries: j0 = i0 + MLEN there)
        const bool last = (jt == ntile - 1);
#pragma unroll
        for (int i = 0; i < 4; i++)
#pragma unroll
            for (int j = 0; j < 4; j++) {
                s[i][j] *= 0.125f;
                if (last && (tx * 4 + j > ty * 4 + i)) s[i][j] = -1e30f;
            }

        // online softmax; rows live on 16 tx lanes (xor 1,2,4,8 stays in-group)
        float tm[4];
#pragma unroll
        for (int i = 0; i < 4; i++) {
            tm[i] = fmaxf(fmaxf(s[i][0], s[i][1]), fmaxf(s[i][2], s[i][3]));
        }
#pragma unroll
        for (int o = 1; o < 16; o <<= 1)
#pragma unroll
            for (int i = 0; i < 4; i++)
                tm[i] = fmaxf(tm[i], __shfl_xor_sync(0xffffffffu, tm[i], o));

        float corr[4], tl[4];
#pragma unroll
        for (int i = 0; i < 4; i++) {
            const float nm = fmaxf(m[i], tm[i]);
            corr[i] = __expf(m[i] - nm);
            m[i] = nm;
            float pl = 0.f;
#pragma unroll
            for (int j = 0; j < 4; j++) { s[i][j] = __expf(s[i][j] - nm); pl += s[i][j]; }
            tl[i] = pl;
        }
#pragma unroll
        for (int o = 1; o < 16; o <<= 1)
#pragma unroll
            for (int i = 0; i < 4; i++)
                tl[i] += __shfl_xor_sync(0xffffffffu, tl[i], o);
#pragma unroll
        for (int i = 0; i < 4; i++) {
            l[i] = l[i] * corr[i] + tl[i];
#pragma unroll
            for (int j = 0; j < 4; j++) acc[i][j] *= corr[i];
            *(float4*)(Ps + (size_t)(ty * 4 + i) * PS_S + tx * 4) =
                make_float4(s[i][0], s[i][1], s[i][2], s[i][3]);
        }
        __syncthreads();   // P visible to all warps

        // PV: acc[i][dd] += P[r0+i][j] * V[j][tx*4+dd]
#pragma unroll 4
        for (int j4 = 0; j4 < 64; j4 += 4) {
            float p0[4], p1[4], p2[4], p3[4];
            *(float4*)p0 = *(const float4*)(Ps + (size_t)(ty * 4 + 0) * PS_S + j4);
            *(float4*)p1 = *(const float4*)(Ps + (size_t)(ty * 4 + 1) * PS_S + j4);
            *(float4*)p2 = *(const float4*)(Ps + (size_t)(ty * 4 + 2) * PS_S + j4);
            *(float4*)p3 = *(const float4*)(Ps + (size_t)(ty * 4 + 3) * PS_S + j4);
#pragma unroll
            for (int jj = 0; jj < 4; jj++) {
                float4 vv = *(const float4*)(Vs + (size_t)(j4 + jj) * VS_S + tx * 4);
                acc[0][0] = fmaf(p0[jj], vv.x, acc[0][0]);
                acc[0][1] = fmaf(p0[jj], vv.y, acc[0][1]);
                acc[0][2] = fmaf(p0[jj], vv.z, acc[0][2]);
                acc[0][3] = fmaf(p0[jj], vv.w, acc[0][3]);
                acc[1][0] = fmaf(p1[jj], vv.x, acc[1][0]);
                acc[1][1] = fmaf(p1[jj], vv.y, acc[1][1]);
                acc[1][2] = fmaf(p1[jj], vv.z, acc[1][2]);
                acc[1][3] = fmaf(p1[jj], vv.w, acc[1][3]);
                acc[2][0] = fmaf(p2[jj], vv.x, acc[2][0]);
                acc[2][1] = fmaf(p2[jj], vv.y, acc[2][1]);
                acc[2][2] = fmaf(p2[jj], vv.z, acc[2][2]);
                acc[2][3] = fmaf(p2[jj], vv.w, acc[2][3]);
                acc[3][0] = fmaf(p3[jj], vv.x, acc[3][0]);
                acc[3][1] = fmaf(p3[jj], vv.y, acc[3][1]);
                acc[3][2] = fmaf(p3[jj], vv.z, acc[3][2]);
                acc[3][3] = fmaf(p3[jj], vv.w, acc[3][3]);
            }
        }
    }

    // epilogue: normalize, store 4 rows x 4 dims per thread (no cross-lane reduce)
#pragma unroll
    for (int i = 0; i < 4; i++) {
        const float inv = 1.f / l[i];
        float4 o4 = make_float4(acc[i][0] * inv, acc[i][1] * inv,
                                acc[i][2] * inv, acc[i][3] * inv);
        *(float4*)(g_AV + ((size_t)(i0 + ty * 4 + i) * BSZ + b) * DM + n * DH + tx * 4) = o4;
    }
}

// ---------------- LayerNorm over last dim (1024) ----------------
__global__ __launch_bounds__(256)
void ln_kernel(const float* __restrict__ gam, const float* __restrict__ bet,
               float* __restrict__ out)
{
    __shared__ float rs[8], rq[8];
    const int row = blockIdx.x;
    const int t = threadIdx.x;
    const float4 v = ((const float4*)(g_Y + (size_t)row * DM))[t];
    float s = v.x + v.y + v.z + v.w;
    float q = v.x * v.x + v.y * v.y + v.z * v.z + v.w * v.w;
#pragma unroll
    for (int o = 16; o; o >>= 1) {
        s += __shfl_down_sync(0xffffffffu, s, o);
        q += __shfl_down_sync(0xffffffffu, q, o);
    }
    if ((t & 31) == 0) { rs[t >> 5] = s; rq[t >> 5] = q; }
    __syncthreads();
    if (t == 0) {
        float ss = 0.f, qq = 0.f;
#pragma unroll
        for (int i = 0; i < 8; i++) { ss += rs[i]; qq += rq[i]; }
        rs[0] = ss; rq[0] = qq;
    }
    __syncthreads();
    const float mu   = rs[0] * (1.f / 1024.f);
    const float var  = rq[0] * (1.f / 1024.f) - mu * mu;
    const float rstd = rsqrtf(var + 1e-5f);
    const float4 g4 = ((const float4*)gam)[t];
    const float4 b4 = ((const float4*)bet)[t];
    float4 o4;
    o4.x = (v.x - mu) * rstd * g4.x + b4.x;
    o4.y = (v.y - mu) * rstd * g4.y + b4.y;
    o4.z = (v.z - mu) * rstd * g4.z + b4.z;
    o4.w = (v.w - mu) * rstd * g4.w + b4.w;
    ((float4*)(out + (size_t)row * DM))[t] = o4;
}

// ---------------- launch ----------------
extern "C" void kernel_launch(void* const* d_in, const int* in_sizes, int n_in,
                              void* d_out, int out_size)
{
    const float* w    = (const float*)d_in[0];
    const float* r    = (const float*)d_in[1];
    const float* rwb  = (const float*)d_in[2];
    const float* rrb  = (const float*)d_in[3];
    const float* mems = (const float*)d_in[4];
    const float* Wq   = (const float*)d_in[5];
    const float* bq   = (const float*)d_in[6];
    const float* Wk   = (const float*)d_in[7];
    const float* bk   = (const float*)d_in[8];
    const float* Wv   = (const float*)d_in[9];
    const float* bv   = (const float*)d_in[10];
    const float* Wr   = (const float*)d_in[11];
    const float* br   = (const float*)d_in[12];
    const float* Wo   = (const float*)d_in[13];
    const float* bo   = (const float*)d_in[14];
    const float* lng  = (const float*)d_in[15];
    const float* lnb  = (const float*)d_in[16];
    float* out = (float*)d_out;

    cudaFuncSetAttribute(attn_kernel,
                         cudaFuncAttributeMaxDynamicSharedMemorySize, ATTN_SMEM_BYTES);

    const dim3 blk(256);
    sgemm_kernel<MODE_Q><<<dim3(8, 32), blk>>>(w, nullptr, Wq, bq, nullptr);
    sgemm_kernel<MODE_K><<<dim3(8, 64), blk>>>(mems, w, Wk, bk, nullptr);
    sgemm_kernel<MODE_V><<<dim3(8, 64), blk>>>(mems, w, Wv, bv, nullptr);
    sgemm_kernel<MODE_R><<<dim3(8, 16), blk>>>(r, nullptr, Wr, br, nullptr);
    attn_kernel<<<dim3(16, 64), blk, ATTN_SMEM_BYTES>>>(rwb, rrb);
    sgemm_kernel<MODE_O><<<dim3(8, 32), blk>>>(nullptr, nullptr, Wo, bo, w);
    ln_kernel<<<QLEN * BSZ, 256>>>(lng, lnb, out);
}

// round 12
// speedup vs baseline: 3.8500x; 1.4355x over previous
#include <cuda_runtime.h>
#include <cuda_bf16.h>
#include <cstdint>
#include <cstddef>

#define QLEN 1024
#define MLEN 1024
#define KLEN 2048
#define BSZ  4
#define DM   1024
#define NH   16
#define DH   64

// ---------------- scratch (device globals; allocation is forbidden) ----------------
__device__ float g_Q [(size_t)BSZ * NH * QLEN * DH];   // [b][n][i][d]
__device__ float g_K [(size_t)BSZ * NH * KLEN * DH];   // [b][n][j][d]
__device__ float g_V [(size_t)BSZ * NH * KLEN * DH];   // [b][n][j][d]
__device__ float g_RK[(size_t)NH * KLEN * DH];         // [n][jr][d]
__device__ float g_AV[(size_t)QLEN * BSZ * DM];        // attn_vec, row = i*BSZ+b
__device__ float g_Y [(size_t)QLEN * BSZ * DM];        // w + attn_out (pre-LN)

// bf16 split operands
__device__ __nv_bfloat16 g_catH[(size_t)2 * QLEN * BSZ * DM];  // [mems;w] rows
__device__ __nv_bfloat16 g_catL[(size_t)2 * QLEN * BSZ * DM];
__device__ __nv_bfloat16 g_rH  [(size_t)KLEN * DM];
__device__ __nv_bfloat16 g_rL  [(size_t)KLEN * DM];
__device__ __nv_bfloat16 g_avH [(size_t)QLEN * BSZ * DM];
__device__ __nv_bfloat16 g_avL [(size_t)QLEN * BSZ * DM];
__device__ __nv_bfloat16 g_WtH [5][(size_t)DM * DM];   // transposed weights [n][k]
__device__ __nv_bfloat16 g_WtL [5][(size_t)DM * DM];

#define MODE_Q 0
#define MODE_K 1
#define MODE_V 2
#define MODE_R 3
#define MODE_O 4

// ---------------- PTX helpers ----------------
__device__ __forceinline__ uint32_t smem_u32(const void* p) {
    uint32_t a;
    asm("{ .reg .u64 t; cvta.to.shared.u64 t, %1; cvt.u32.u64 %0, t; }"
        : "=r"(a) : "l"(p));
    return a;
}
__device__ __forceinline__ void ldsm_x4(uint32_t* r, uint32_t addr) {
    asm volatile("ldmatrix.sync.aligned.m8n8.x4.shared.b16 {%0,%1,%2,%3}, [%4];"
                 : "=r"(r[0]), "=r"(r[1]), "=r"(r[2]), "=r"(r[3]) : "r"(addr));
}
__device__ __forceinline__ void ldsm_x2(uint32_t* r, uint32_t addr) {
    asm volatile("ldmatrix.sync.aligned.m8n8.x2.shared.b16 {%0,%1}, [%2];"
                 : "=r"(r[0]), "=r"(r[1]) : "r"(addr));
}
__device__ __forceinline__ void mma16816(float* c, const uint32_t* a, const uint32_t* b) {
    asm volatile(
        "mma.sync.aligned.m16n8k16.row.col.f32.bf16.bf16.f32 "
        "{%0,%1,%2,%3}, {%4,%5,%6,%7}, {%8,%9}, {%0,%1,%2,%3};"
        : "+f"(c[0]), "+f"(c[1]), "+f"(c[2]), "+f"(c[3])
        : "r"(a[0]), "r"(a[1]), "r"(a[2]), "r"(a[3]), "r"(b[0]), "r"(b[1]));
}

// ---------------- conversion kernels ----------------
__global__ void split_kernel(const float* __restrict__ in,
                             __nv_bfloat16* __restrict__ hi,
                             __nv_bfloat16* __restrict__ lo, int n4)
{
    int i = blockIdx.x * blockDim.x + threadIdx.x;
    if (i >= n4) return;
    float4 v = ((const float4*)in)[i];
    __nv_bfloat16 h0 = __float2bfloat16(v.x), h1 = __float2bfloat16(v.y);
    __nv_bfloat16 h2 = __float2bfloat16(v.z), h3 = __float2bfloat16(v.w);
    __nv_bfloat16 l0 = __float2bfloat16(v.x - __bfloat162float(h0));
    __nv_bfloat16 l1 = __float2bfloat16(v.y - __bfloat162float(h1));
    __nv_bfloat16 l2 = __float2bfloat16(v.z - __bfloat162float(h2));
    __nv_bfloat16 l3 = __float2bfloat16(v.w - __bfloat162float(h3));
    ((__nv_bfloat162*)hi)[2 * i]     = __halves2bfloat162(h0, h1);
    ((__nv_bfloat162*)hi)[2 * i + 1] = __halves2bfloat162(h2, h3);
    ((__nv_bfloat162*)lo)[2 * i]     = __halves2bfloat162(l0, l1);
    ((__nv_bfloat162*)lo)[2 * i + 1] = __halves2bfloat162(l2, l3);
}

// W[k][n] (1024x1024) -> Wt[n][k] split hi/lo
__global__ void wsplit_kernel(const float* __restrict__ W,
                              __nv_bfloat16* __restrict__ hi,
                              __nv_bfloat16* __restrict__ lo)
{
    __shared__ float tile[32][33];
    const int k0 = blockIdx.y * 32, n0 = blockIdx.x * 32;
    const int tx = threadIdx.x, ty = threadIdx.y;
    for (int r = ty; r < 32; r += 8)
        tile[r][tx] = W[(size_t)(k0 + r) * DM + n0 + tx];
    __syncthreads();
    for (int r = ty; r < 32; r += 8) {
        float v = tile[tx][r];   // = W[k0+tx][n0+r]
        __nv_bfloat16 h = __float2bfloat16(v);
        __nv_bfloat16 l = __float2bfloat16(v - __bfloat162float(h));
        hi[(size_t)(n0 + r) * DM + k0 + tx] = h;
        lo[(size_t)(n0 + r) * DM + k0 + tx] = l;
    }
}

// ---------------- mma.sync split-bf16 GEMM: C[M,1024] = A @ W + bias ----------------
// CTA tile 128x128, K-chunk 64 bf16. smem: AH|AL|BH|BL at padded stride 72.
#define KS   64
#define STR  72
#define MAT_BF (128 * STR)                      // 9216 bf16 per matrix
#define GEMM_SMEM_BYTES (4 * MAT_BF * 2)        // 73728 B

template <int MODE>
__global__ __launch_bounds__(256, 2)
void tgemm_kernel(const __nv_bfloat16* __restrict__ AH,
                  const __nv_bfloat16* __restrict__ AL,
                  const __nv_bfloat16* __restrict__ BH,
                  const __nv_bfloat16* __restrict__ BL,
                  const float* __restrict__ bias,
                  const float* __restrict__ addend)
{
    extern __shared__ __align__(16) __nv_bfloat16 smb[];
    __nv_bfloat16* sAH = smb;
    __nv_bfloat16* sAL = smb + MAT_BF;
    __nv_bfloat16* sBH = smb + 2 * MAT_BF;
    __nv_bfloat16* sBL = smb + 3 * MAT_BF;

    const int t    = threadIdx.x;
    const int wid  = t >> 5;
    const int lane = t & 31;
    const int wm   = wid >> 2;     // 0..1 -> 64 rows
    const int wn   = wid & 3;      // 0..3 -> 32 cols
    const int m0   = blockIdx.y * 128;
    const int n0   = blockIdx.x * 128;

    const uint32_t sAHu = smem_u32(sAH), sALu = smem_u32(sAL);
    const uint32_t sBHu = smem_u32(sBH), sBLu = smem_u32(sBL);

    // ldmatrix lane->address offsets (in bf16 elems)
    const int aoff = (lane & 15) * STR + ((lane >> 4) << 3);        // x4: rows 0..15, k +8
    const int boff = (lane & 7) * STR + (((lane >> 3) & 1) << 3);   // x2: rows 0..7,  k +8

    float acc[4][4][4];
#pragma unroll
    for (int i = 0; i < 4; i++)
#pragma unroll
        for (int j = 0; j < 4; j++)
#pragma unroll
            for (int k = 0; k < 4; k++) acc[i][j][k] = 0.f;

    for (int c = 0; c < 16; c++) {
        __syncthreads();   // previous chunk consumed
        const size_t coff = (size_t)c * KS;
#pragma unroll
        for (int i = 0; i < 4; i++) {
            const int idx = t + i * 256;        // 1024 uint4 items per matrix
            const int row = idx >> 3, g = (idx & 7) * 8;
            *(uint4*)(sAH + row * STR + g) = *(const uint4*)(AH + (size_t)(m0 + row) * DM + coff + g);
            *(uint4*)(sAL + row * STR + g) = *(const uint4*)(AL + (size_t)(m0 + row) * DM + coff + g);
            *(uint4*)(sBH + row * STR + g) = *(const uint4*)(BH + (size_t)(n0 + row) * DM + coff + g);
            *(uint4*)(sBL + row * STR + g) = *(const uint4*)(BL + (size_t)(n0 + row) * DM + coff + g);
        }
        __syncthreads();

#pragma unroll
        for (int ks = 0; ks < KS; ks += 16) {
            uint32_t bh[4][2], bl[4][2];
#pragma unroll
            for (int nt = 0; nt < 4; nt++) {
                const int nrow = wn * 32 + nt * 8;
                ldsm_x2(bh[nt], sBHu + (uint32_t)(nrow * STR + ks + boff) * 2);
                ldsm_x2(bl[nt], sBLu + (uint32_t)(nrow * STR + ks + boff) * 2);
            }
#pragma unroll
            for (int mt = 0; mt < 4; mt++) {
                const int mrow = wm * 64 + mt * 16;
                uint32_t ah[4], al[4];
                ldsm_x4(ah, sAHu + (uint32_t)(mrow * STR + ks + aoff) * 2);
                ldsm_x4(al, sALu + (uint32_t)(mrow * STR + ks + aoff) * 2);
#pragma unroll
                for (int nt = 0; nt < 4; nt++) {
                    mma16816(acc[mt][nt], ah, bh[nt]);
                    mma16816(acc[mt][nt], ah, bl[nt]);
                    mma16816(acc[mt][nt], al, bh[nt]);
                }
            }
        }
    }

    // epilogue: c-fragment -> bias + mode scatter (float2, col pairs share head)
    const int g  = lane >> 2;
    const int cp = (lane & 3) * 2;
#pragma unroll
    for (int mt = 0; mt < 4; mt++) {
        const int rbase = m0 + wm * 64 + mt * 16;
#pragma unroll
        for (int nt = 0; nt < 4; nt++) {
            const int col = n0 + wn * 32 + nt * 8 + cp;
            const float b0 = bias[col], b1 = bias[col + 1];
            const int nn = col >> 6, d = col & 63;
#pragma unroll
            for (int hrow = 0; hrow < 2; hrow++) {
                const int row = rbase + g + hrow * 8;
                float v0 = acc[mt][nt][hrow * 2 + 0] + b0;
                float v1 = acc[mt][nt][hrow * 2 + 1] + b1;
                if (MODE == MODE_O) {
                    const float2 ad = *(const float2*)(addend + (size_t)row * DM + col);
                    *(float2*)(g_Y + (size_t)row * DM + col) =
                        make_float2(v0 + ad.x, v1 + ad.y);
                } else if (MODE == MODE_R) {
                    *(float2*)(g_RK + ((size_t)nn * KLEN + row) * DH + d) =
                        make_float2(v0, v1);
                } else if (MODE == MODE_Q) {
                    const int ip = row >> 2, bb = row & 3;
                    *(float2*)(g_Q + (((size_t)bb * NH + nn) * QLEN + ip) * DH + d) =
                        make_float2(v0, v1);
                } else {
                    const int ip = row >> 2, bb = row & 3;
                    float* dst = (MODE == MODE_K) ? g_K : g_V;
                    *(float2*)(dst + (((size_t)bb * NH + nn) * KLEN + ip) * DH + d) =
                        make_float2(v0, v1);
                }
            }
        }
    }
}

// ---------------- flash attention, register-tiled (4x4 per thread) ----------------
#define QT_S 68
#define KS_S 68
#define VS_S 68
#define PS_S 68
#define RS_S 129
#define OFF_QT 0
#define OFF_KS (OFF_QT + 64 * QT_S)
#define OFF_VS (OFF_KS + 64 * KS_S)
#define OFF_PS (OFF_VS + 64 * VS_S)
#define OFF_RS (OFF_PS + 64 * PS_S)
#define OFF_DB (OFF_RS + 64 * RS_S)
#define OFF_BDC (OFF_DB + 64)
#define ATTN_SMEM_FLOATS (OFF_BDC + 128)
#define ATTN_SMEM_BYTES (ATTN_SMEM_FLOATS * 4)

__global__ __launch_bounds__(256, 2)
void attn_kernel(const float* __restrict__ rwb, const float* __restrict__ rrb)
{
    extern __shared__ float sm[];
    float* qwT = sm + OFF_QT;
    float* KsT = sm + OFF_KS;
    float* Vs  = sm + OFF_VS;
    float* Ps  = sm + OFF_PS;
    float* RsT = sm + OFF_RS;
    float* db  = sm + OFF_DB;
    float* BDc = sm + OFF_BDC;

    const int t  = threadIdx.x;
    const int qt = 15 - (int)blockIdx.x;
    const int i0 = qt * 64;
    const int h  = blockIdx.y;
    const int b  = h >> 4;
    const int n  = h & 15;
    const int tx = t & 15;
    const int ty = t >> 4;

    const float* Qh = g_Q  + ((size_t)b * NH + n) * QLEN * DH;
    const float* Kh = g_K  + ((size_t)b * NH + n) * KLEN * DH;
    const float* Vh = g_V  + ((size_t)b * NH + n) * KLEN * DH;
    const float* Rh = g_RK + (size_t)n * KLEN * DH;

    if (t < 64) db[t] = rrb[n * DH + t] - rwb[n * DH + t];
    for (int e = t; e < 64 * 16; e += 256) {
        const int r = e >> 4, d = (e & 15) * 4;
        float4 q4 = *(const float4*)(Qh + (size_t)(i0 + r) * DH + d);
        float4 w4 = *(const float4*)(rwb + n * DH + d);
        qwT[(d + 0) * QT_S + r] = q4.x + w4.x;
        qwT[(d + 1) * QT_S + r] = q4.y + w4.y;
        qwT[(d + 2) * QT_S + r] = q4.z + w4.z;
        qwT[(d + 3) * QT_S + r] = q4.w + w4.w;
    }

    float m[4], l[4], acc[4][4];
#pragma unroll
    for (int i = 0; i < 4; i++) {
        m[i] = -1e30f; l[i] = 0.f;
#pragma unroll
        for (int j = 0; j < 4; j++) acc[i][j] = 0.f;
    }

    const int dbase = tx * 4 - ty * 4 + 63;
    const int ntile = qt + 17;

    for (int jt = 0; jt < ntile; jt++) {
        const int j0 = jt * 64;
        __syncthreads();

        for (int e = t; e < 64 * 16; e += 256) {
            const int c = e >> 4, d = (e & 15) * 4;
            float4 k4 = *(const float4*)(Kh + (size_t)(j0 + c) * DH + d);
            KsT[(d + 0) * KS_S + c] = k4.x;
            KsT[(d + 1) * KS_S + c] = k4.y;
            KsT[(d + 2) * KS_S + c] = k4.z;
            KsT[(d + 3) * KS_S + c] = k4.w;
            *(float4*)(Vs + (size_t)c * VS_S + d) =
                *(const float4*)(Vh + (size_t)(j0 + c) * DH + d);
        }
        const int rb = j0 - i0 + (QLEN - 64);
        for (int e = t; e < 128 * 16; e += 256) {
            const int ri = e & 127, d = (e >> 7) * 4;
            const int jr = rb + ri;
            float4 r4 = make_float4(0.f, 0.f, 0.f, 0.f);
            if (jr < KLEN) r4 = *(const float4*)(Rh + (size_t)jr * DH + d);
            RsT[(d + 0) * RS_S + ri] = r4.x;
            RsT[(d + 1) * RS_S + ri] = r4.y;
            RsT[(d + 2) * RS_S + ri] = r4.z;
            RsT[(d + 3) * RS_S + ri] = r4.w;
        }
        __syncthreads();

        if (t < 128) {
            float sum = 0.f;
#pragma unroll 8
            for (int d = 0; d < 64; d++) sum = fmaf(db[d], RsT[d * RS_S + t], sum);
            BDc[t] = sum;
        }
        __syncthreads();

        float s[4][4];
#pragma unroll
        for (int i = 0; i < 4; i++)
#pragma unroll
            for (int j = 0; j < 4; j++)
                s[i][j] = BDc[dbase + j - i];

#pragma unroll 4
        for (int d = 0; d < 64; d++) {
            float4 qv = *(const float4*)(qwT + d * QT_S + ty * 4);
            float4 kv = *(const float4*)(KsT + d * KS_S + tx * 4);
            const float* rp = RsT + d * RS_S + (dbase - 3);
            float rr[7];
#pragma unroll
            for (int o = 0; o < 7; o++) rr[o] = rp[o];
            float qq[4] = {qv.x, qv.y, qv.z, qv.w};
            float kk[4] = {kv.x, kv.y, kv.z, kv.w};
#pragma unroll
            for (int i = 0; i < 4; i++)
#pragma unroll
                for (int j = 0; j < 4; j++)
                    s[i][j] = fmaf(qq[i], kk[j] + rr[3 + j - i], s[i][j]);
        }

        const bool last = (jt == ntile - 1);
#pragma unroll
        for (int i = 0; i < 4; i++)
#pragma unroll
            for (int j = 0; j < 4; j++) {
                s[i][j] *= 0.125f;
                if (last && (tx * 4 + j > ty * 4 + i)) s[i][j] = -1e30f;
            }

        float tm[4];
#pragma unroll
        for (int i = 0; i < 4; i++)
            tm[i] = fmaxf(fmaxf(s[i][0], s[i][1]), fmaxf(s[i][2], s[i][3]));
#pragma unroll
        for (int o = 1; o < 16; o <<= 1)
#pragma unroll
            for (int i = 0; i < 4; i++)
                tm[i] = fmaxf(tm[i], __shfl_xor_sync(0xffffffffu, tm[i], o));

        float corr[4], tl[4];
#pragma unroll
        for (int i = 0; i < 4; i++) {
            const float nm = fmaxf(m[i], tm[i]);
            corr[i] = __expf(m[i] - nm);
            m[i] = nm;
            float pl = 0.f;
#pragma unroll
            for (int j = 0; j < 4; j++) { s[i][j] = __expf(s[i][j] - nm); pl += s[i][j]; }
            tl[i] = pl;
        }
#pragma unroll
        for (int o = 1; o < 16; o <<= 1)
#pragma unroll
            for (int i = 0; i < 4; i++)
                tl[i] += __shfl_xor_sync(0xffffffffu, tl[i], o);
#pragma unroll
        for (int i = 0; i < 4; i++) {
            l[i] = l[i] * corr[i] + tl[i];
#pragma unroll
            for (int j = 0; j < 4; j++) acc[i][j] *= corr[i];
            *(float4*)(Ps + (size_t)(ty * 4 + i) * PS_S + tx * 4) =
                make_float4(s[i][0], s[i][1], s[i][2], s[i][3]);
        }
        __syncthreads();

#pragma unroll 4
        for (int j4 = 0; j4 < 64; j4 += 4) {
            float p0[4], p1[4], p2[4], p3[4];
            *(float4*)p0 = *(const float4*)(Ps + (size_t)(ty * 4 + 0) * PS_S + j4);
            *(float4*)p1 = *(const float4*)(Ps + (size_t)(ty * 4 + 1) * PS_S + j4);
            *(float4*)p2 = *(const float4*)(Ps + (size_t)(ty * 4 + 2) * PS_S + j4);
            *(float4*)p3 = *(const float4*)(Ps + (size_t)(ty * 4 + 3) * PS_S + j4);
#pragma unroll
            for (int jj = 0; jj < 4; jj++) {
                float4 vv = *(const float4*)(Vs + (size_t)(j4 + jj) * VS_S + tx * 4);
                acc[0][0] = fmaf(p0[jj], vv.x, acc[0][0]);
                acc[0][1] = fmaf(p0[jj], vv.y, acc[0][1]);
                acc[0][2] = fmaf(p0[jj], vv.z, acc[0][2]);
                acc[0][3] = fmaf(p0[jj], vv.w, acc[0][3]);
                acc[1][0] = fmaf(p1[jj], vv.x, acc[1][0]);
                acc[1][1] = fmaf(p1[jj], vv.y, acc[1][1]);
                acc[1][2] = fmaf(p1[jj], vv.z, acc[1][2]);
                acc[1][3] = fmaf(p1[jj], vv.w, acc[1][3]);
                acc[2][0] = fmaf(p2[jj], vv.x, acc[2][0]);
                acc[2][1] = fmaf(p2[jj], vv.y, acc[2][1]);
                acc[2][2] = fmaf(p2[jj], vv.z, acc[2][2]);
                acc[2][3] = fmaf(p2[jj], vv.w, acc[2][3]);
                acc[3][0] = fmaf(p3[jj], vv.x, acc[3][0]);
                acc[3][1] = fmaf(p3[jj], vv.y, acc[3][1]);
                acc[3][2] = fmaf(p3[jj], vv.z, acc[3][2]);
                acc[3][3] = fmaf(p3[jj], vv.w, acc[3][3]);
            }
        }
    }

#pragma unroll
    for (int i = 0; i < 4; i++) {
        const float inv = 1.f / l[i];
        float4 o4 = make_float4(acc[i][0] * inv, acc[i][1] * inv,
                                acc[i][2] * inv, acc[i][3] * inv);
        *(float4*)(g_AV + ((size_t)(i0 + ty * 4 + i) * BSZ + b) * DM + n * DH + tx * 4) = o4;
    }
}

// ---------------- LayerNorm over last dim (1024) ----------------
__global__ __launch_bounds__(256)
void ln_kernel(const float* __restrict__ gam, const float* __restrict__ bet,
               float* __restrict__ out)
{
    __shared__ float rs[8], rq[8];
    const int row = blockIdx.x;
    const int t = threadIdx.x;
    const float4 v = ((const float4*)(g_Y + (size_t)row * DM))[t];
    float s = v.x + v.y + v.z + v.w;
    float q = v.x * v.x + v.y * v.y + v.z * v.z + v.w * v.w;
#pragma unroll
    for (int o = 16; o; o >>= 1) {
        s += __shfl_down_sync(0xffffffffu, s, o);
        q += __shfl_down_sync(0xffffffffu, q, o);
    }
    if ((t & 31) == 0) { rs[t >> 5] = s; rq[t >> 5] = q; }
    __syncthreads();
    if (t == 0) {
        float ss = 0.f, qq = 0.f;
#pragma unroll
        for (int i = 0; i < 8; i++) { ss += rs[i]; qq += rq[i]; }
        rs[0] = ss; rq[0] = qq;
    }
    __syncthreads();
    const float mu   = rs[0] * (1.f / 1024.f);
    const float var  = rq[0] * (1.f / 1024.f) - mu * mu;
    const float rstd = rsqrtf(var + 1e-5f);
    const float4 g4 = ((const float4*)gam)[t];
    const float4 b4 = ((const float4*)bet)[t];
    float4 o4;
    o4.x = (v.x - mu) * rstd * g4.x + b4.x;
    o4.y = (v.y - mu) * rstd * g4.y + b4.y;
    o4.z = (v.z - mu) * rstd * g4.z + b4.z;
    o4.w = (v.w - mu) * rstd * g4.w + b4.w;
    ((float4*)(out + (size_t)row * DM))[t] = o4;
}

// ---------------- launch ----------------
extern "C" void kernel_launch(void* const* d_in, const int* in_sizes, int n_in,
                              void* d_out, int out_size)
{
    const float* w    = (const float*)d_in[0];
    const float* r    = (const float*)d_in[1];
    const float* rwb  = (const float*)d_in[2];
    const float* rrb  = (const float*)d_in[3];
    const float* mems = (const float*)d_in[4];
    const float* Wq   = (const float*)d_in[5];
    const float* bq   = (const float*)d_in[6];
    const float* Wk   = (const float*)d_in[7];
    const float* bk   = (const float*)d_in[8];
    const float* Wv   = (const float*)d_in[9];
    const float* bv   = (const float*)d_in[10];
    const float* Wr   = (const float*)d_in[11];
    const float* br   = (const float*)d_in[12];
    const float* Wo   = (const float*)d_in[13];
    const float* bo   = (const float*)d_in[14];
    const float* lng  = (const float*)d_in[15];
    const float* lnb  = (const float*)d_in[16];
    float* out = (float*)d_out;

    cudaFuncSetAttribute(attn_kernel, cudaFuncAttributeMaxDynamicSharedMemorySize,
                         ATTN_SMEM_BYTES);
    cudaFuncSetAttribute(tgemm_kernel<MODE_Q>, cudaFuncAttributeMaxDynamicSharedMemorySize, GEMM_SMEM_BYTES);
    cudaFuncSetAttribute(tgemm_kernel<MODE_K>, cudaFuncAttributeMaxDynamicSharedMemorySize, GEMM_SMEM_BYTES);
    cudaFuncSetAttribute(tgemm_kernel<MODE_V>, cudaFuncAttributeMaxDynamicSharedMemorySize, GEMM_SMEM_BYTES);
    cudaFuncSetAttribute(tgemm_kernel<MODE_R>, cudaFuncAttributeMaxDynamicSharedMemorySize, GEMM_SMEM_BYTES);
    cudaFuncSetAttribute(tgemm_kernel<MODE_O>, cudaFuncAttributeMaxDynamicSharedMemorySize, GEMM_SMEM_BYTES);

    // resolve device-global addresses host-side
    __nv_bfloat16 *catH, *catL, *rH, *rL, *avH, *avL, *WtH, *WtL;
    cudaGetSymbolAddress((void**)&catH, g_catH);
    cudaGetSymbolAddress((void**)&catL, g_catL);
    cudaGetSymbolAddress((void**)&rH, g_rH);
    cudaGetSymbolAddress((void**)&rL, g_rL);
    cudaGetSymbolAddress((void**)&avH, g_avH);
    cudaGetSymbolAddress((void**)&avL, g_avL);
    cudaGetSymbolAddress((void**)&WtH, g_WtH);
    cudaGetSymbolAddress((void**)&WtL, g_WtL);
    float* AV;
    cudaGetSymbolAddress((void**)&AV, g_AV);

    const int NW = 4096 * 1024 / 4;   // float4 count for 4096x1024
    const dim3 blk(256);
    // splits: [mems; w] -> cat, r -> rH/L
    split_kernel<<<NW / 256, blk>>>(mems, catH, catL, NW);
    split_kernel<<<NW / 256, blk>>>(w, catH + (size_t)4096 * DM, catL + (size_t)4096 * DM, NW);
    split_kernel<<<(KLEN * DM / 4) / 256, blk>>>(r, rH, rL, KLEN * DM / 4);
    // weights: transpose + split
    const dim3 wgrid(32, 32), wblk(32, 8);
    wsplit_kernel<<<wgrid, wblk>>>(Wq, WtH + 0 * (size_t)DM * DM, WtL + 0 * (size_t)DM * DM);
    wsplit_kernel<<<wgrid, wblk>>>(Wk, WtH + 1 * (size_t)DM * DM, WtL + 1 * (size_t)DM * DM);
    wsplit_kernel<<<wgrid, wblk>>>(Wv, WtH + 2 * (size_t)DM * DM, WtL + 2 * (size_t)DM * DM);
    wsplit_kernel<<<wgrid, wblk>>>(Wr, WtH + 3 * (size_t)DM * DM, WtL + 3 * (size_t)DM * DM);
    wsplit_kernel<<<wgrid, wblk>>>(Wo, WtH + 4 * (size_t)DM * DM, WtL + 4 * (size_t)DM * DM);

    // projections on tensor cores (mma.sync)
    tgemm_kernel<MODE_Q><<<dim3(8, 32), blk, GEMM_SMEM_BYTES>>>(
        catH + (size_t)4096 * DM, catL + (size_t)4096 * DM,
        WtH + 0 * (size_t)DM * DM, WtL + 0 * (size_t)DM * DM, bq, nullptr);
    tgemm_kernel<MODE_K><<<dim3(8, 64), blk, GEMM_SMEM_BYTES>>>(
        catH, catL, WtH + 1 * (size_t)DM * DM, WtL + 1 * (size_t)DM * DM, bk, nullptr);
    tgemm_kernel<MODE_V><<<dim3(8, 64), blk, GEMM_SMEM_BYTES>>>(
        catH, catL, WtH + 2 * (size_t)DM * DM, WtL + 2 * (size_t)DM * DM, bv, nullptr);
    tgemm_kernel<MODE_R><<<dim3(8, 16), blk, GEMM_SMEM_BYTES>>>(
        rH, rL, WtH + 3 * (size_t)DM * DM, WtL + 3 * (size_t)DM * DM, br, nullptr);

    // attention
    attn_kernel<<<dim3(16, 64), blk, ATTN_SMEM_BYTES>>>(rwb, rrb);

    // output projection (+residual) and LayerNorm
    split_kernel<<<NW / 256, blk>>>(AV, avH, avL, NW);
    tgemm_kernel<MODE_O><<<dim3(8, 32), blk, GEMM_SMEM_BYTES>>>(
        avH, avL, WtH + 4 * (size_t)DM * DM, WtL + 4 * (size_t)DM * DM, bo, w);
    ln_kernel<<<QLEN * BSZ, 256>>>(lng, lnb, out);
}